// round 16
// baseline (speedup 1.0000x reference)
#include <cuda_runtime.h>
#include <cstdint>

#define NU 100000
#define NP 50000
#define NN 150000   // NU + NP
#define NE 250000
#define D  256

// ---------------- scratch (static device globals; no allocation) ----------------
__device__ float g_x[(size_t)NN * D];    // conv input chain (tf32-rounded at write)
__device__ float g_h[(size_t)NN * D];    // conv1 out (scaled) / MLP partials
__device__ float g_h2[(size_t)NN * D];   // conv2 out (scaled)  — double buffer
__device__ float g_dinv[NN];
__device__ int   g_deg[NN];
__device__ int   g_off[NN];
__device__ int   g_cur[NN];
__device__ int   g_total;
__device__ int   g_adj[2 * NE];
__device__ int   g_aid[2 * NE];
__device__ float g_wt[327680];
#define WT_U  0
#define WT_P  32768
#define WT_C1 65536
#define WT_C2 131072
#define WT_M1 196608

// ================= helpers =================
__device__ __forceinline__ uint32_t smem_u32(const void* p) {
    uint32_t a;
    asm("{ .reg .u64 t; cvta.to.shared.u64 t, %1; cvt.u32.u64 %0, t; }" : "=r"(a) : "l"(p));
    return a;
}
__device__ __forceinline__ uint32_t totf32(float x) {
    uint32_t u;
    asm("cvt.rna.tf32.f32 %0, %1;" : "=r"(u) : "f"(x));
    return u;
}
__device__ __forceinline__ uint32_t tf32r(uint32_t x) { return totf32(__uint_as_float(x)); }
__device__ __forceinline__ float tf32f(float x) { return __uint_as_float(totf32(x)); }
#define SWZ(off) ((off) ^ (((off) >> 3) & 0x70))
#define LDSM_X4(r0, r1, r2, r3, addr) \
    asm volatile("ldmatrix.sync.aligned.m8n8.x4.shared.b16 {%0, %1, %2, %3}, [%4];" \
                 : "=r"(r0), "=r"(r1), "=r"(r2), "=r"(r3) : "r"(addr))
#define MMA_TF32(c, a0, a1, a2, a3, b0, b1) \
    asm volatile("mma.sync.aligned.m16n8k8.row.col.f32.tf32.tf32.f32 " \
                 "{%0, %1, %2, %3}, {%4, %5, %6, %7}, {%8, %9}, {%0, %1, %2, %3};" \
                 : "+f"((c)[0]), "+f"((c)[1]), "+f"((c)[2]), "+f"((c)[3]) \
                 : "r"(a0), "r"(a1), "r"(a2), "r"(a3), "r"(b0), "r"(b1))
#define CP_ASYNC16(dst, src, sz) \
    asm volatile("cp.async.cg.shared.global [%0], [%1], 16, %2;" \
                 :: "r"(dst), "l"(src), "r"(sz) : "memory")
#define CP_COMMIT() asm volatile("cp.async.commit_group;" ::: "memory")
#define CP_WAIT1()  asm volatile("cp.async.wait_group 1;" ::: "memory")

// ================= degree / CSR build =================
__global__ void k_degree(const int* __restrict__ ei) {
    int e = blockIdx.x * blockDim.x + threadIdx.x;
    if (e < NE) {
        atomicAdd(&g_deg[ei[e]], 1);
        atomicAdd(&g_deg[ei[NE + e]], 1);
    }
}
__global__ void k_offsets() {
    int n = blockIdx.x * blockDim.x + threadIdx.x;
    int lane = threadIdx.x & 31;
    int d = (n < NN) ? g_deg[n] : 0;
    int incl = d;
    #pragma unroll
    for (int o = 1; o < 32; o <<= 1) {
        int t = __shfl_up_sync(0xFFFFFFFFu, incl, o);
        if (lane >= o) incl += t;
    }
    int excl = incl - d;
    int base = 0;
    if (lane == 31) base = atomicAdd(&g_total, incl);
    base = __shfl_sync(0xFFFFFFFFu, base, 31);
    if (n < NN) {
        g_off[n] = base + excl;
        g_cur[n] = 0;
        g_dinv[n] = rsqrtf((float)d + 1.0f);
    }
}
__global__ void k_fill(const int* __restrict__ ei) {
    int e = blockIdx.x * blockDim.x + threadIdx.x;
    if (e >= NE) return;
    int u = ei[e];
    int p = ei[NE + e];
    int idx = g_off[p] + atomicAdd(&g_cur[p], 1);
    g_adj[idx] = u;  g_aid[idx] = e;
    int idx2 = g_off[u] + atomicAdd(&g_cur[u], 1);
    g_adj[idx2] = p; g_aid[idx2] = e;
}

// ========= weight transpose + tf32 pre-round =========
__global__ void k_transpose(const float* __restrict__ W, float* __restrict__ Wt, int K, int N) {
    __shared__ float t[32][33];
    int bn = blockIdx.x * 32, bk = blockIdx.y * 32;
    #pragma unroll
    for (int i = 0; i < 4; i++) {
        int k = bk + threadIdx.y + i * 8, n = bn + threadIdx.x;
        if (k < K && n < N) t[threadIdx.y + i * 8][threadIdx.x] = W[(size_t)k * N + n];
    }
    __syncthreads();
    #pragma unroll
    for (int i = 0; i < 4; i++) {
        int n = bn + threadIdx.y + i * 8, k = bk + threadIdx.x;
        if (k < K && n < N)
            Wt[(size_t)n * K + k] = tf32f(t[threadIdx.x][threadIdx.y + i * 8]);
    }
}

// ================= tf32 mma.sync GEMM body (unchanged core) =================
#define NSTAGE 3
#define STAGE_BYTES 32768
#define GEMM_SMEM (NSTAGE * STAGE_BYTES)

template<bool ROUND_A, bool ROUND_OUT>
__device__ __forceinline__ void gemm_body(const float* __restrict__ A,
                                          const float* __restrict__ Bt, int ldb,
                                          const float* __restrict__ bias,
                                          const float* __restrict__ emb,
                                          const float* __restrict__ rowscale,
                                          float* __restrict__ C,
                                          int M, int K, int blkx, int blky,
                                          uint32_t sb) {
    int tid = threadIdx.x;
    int lane = tid & 31;
    int wid = tid >> 5;
    int warpM = wid & 3;
    int warpN = wid >> 2;
    int rowBase = blkx * 128;
    int colBase = blky * 128;

    float acc[2][8][4];
    #pragma unroll
    for (int mt = 0; mt < 2; mt++)
        #pragma unroll
        for (int j = 0; j < 8; j++)
            #pragma unroll
            for (int q = 0; q < 4; q++) acc[mt][j][q] = 0.f;

    const int fr  = tid >> 3;
    const int fc4 = tid & 7;
    const float* aSrcBase = A  + (size_t)(rowBase + fr) * K + fc4 * 4;
    const float* bSrcBase = Bt + (size_t)(colBase + fr) * ldb + fc4 * 4;

    #define ISSUE_CHUNK(c)                                                         \
        {                                                                          \
            int k0 = (c) << 5;                                                     \
            uint32_t abase = sb + ((c) % NSTAGE) * STAGE_BYTES;                    \
            uint32_t bbase = abase + 16384;                                        \
            _Pragma("unroll")                                                      \
            for (int i = 0; i < 4; i++) {                                          \
                int r = fr + i * 32;                                               \
                uint32_t off = SWZ((uint32_t)(r * 128 + fc4 * 16));                \
                uint32_t asz = (rowBase + r < M) ? 16u : 0u;                       \
                CP_ASYNC16(abase + off, aSrcBase + (size_t)(i * 32) * K + k0, asz);\
                CP_ASYNC16(bbase + off, bSrcBase + (size_t)(i * 32) * ldb + k0, 16u);\
            }                                                                      \
        }

    const int arow = warpM * 32 + (lane & 15);
    const int achunkoff = (lane >> 4);
    const int brow = warpN * 64 + ((lane >> 4) << 3) + (lane & 7);
    const int bchunkoff = ((lane >> 3) & 1);

    const int CH = K >> 5;
    ISSUE_CHUNK(0); CP_COMMIT();
    if (CH > 1) { ISSUE_CHUNK(1); }
    CP_COMMIT();

    for (int ch = 0; ch < CH; ch++) {
        CP_WAIT1();
        __syncthreads();
        if (ch + NSTAGE - 1 < CH) { ISSUE_CHUNK(ch + NSTAGE - 1); }
        CP_COMMIT();

        uint32_t abase = sb + (ch % NSTAGE) * STAGE_BYTES;
        uint32_t bbase = abase + 16384;
        #pragma unroll
        for (int ks = 0; ks < 4; ks++) {
            uint32_t af[2][4];
            #pragma unroll
            for (int mt = 0; mt < 2; mt++) {
                int r = arow + mt * 16;
                uint32_t addr = abase + SWZ((uint32_t)(r * 128 + (2 * ks + achunkoff) * 16));
                LDSM_X4(af[mt][0], af[mt][1], af[mt][2], af[mt][3], addr);
                if (ROUND_A) {
                    #pragma unroll
                    for (int q = 0; q < 4; q++) af[mt][q] = tf32r(af[mt][q]);
                }
            }
            uint32_t bf[4][4];
            #pragma unroll
            for (int jp = 0; jp < 4; jp++) {
                int r = brow + jp * 16;
                uint32_t addr = bbase + SWZ((uint32_t)(r * 128 + (2 * ks + bchunkoff) * 16));
                LDSM_X4(bf[jp][0], bf[jp][1], bf[jp][2], bf[jp][3], addr);
            }
            #pragma unroll
            for (int mt = 0; mt < 2; mt++)
                #pragma unroll
                for (int j = 0; j < 8; j++)
                    MMA_TF32(acc[mt][j], af[mt][0], af[mt][1], af[mt][2], af[mt][3],
                             bf[j >> 1][(j & 1) * 2], bf[j >> 1][(j & 1) * 2 + 1]);
        }
    }

    #pragma unroll
    for (int mt = 0; mt < 2; mt++) {
        int r0 = rowBase + warpM * 32 + mt * 16 + (lane >> 2);
        int r1 = r0 + 8;
        float s0 = (rowscale && r0 < M) ? rowscale[r0] : 1.f;
        float s1 = (rowscale && r1 < M) ? rowscale[r1] : 1.f;
        #pragma unroll
        for (int j = 0; j < 8; j++) {
            int gc = colBase + warpN * 64 + j * 8 + (lane & 3) * 2;
            float2 v0 = make_float2(acc[mt][j][0] * s0, acc[mt][j][1] * s0);
            float2 v1 = make_float2(acc[mt][j][2] * s1, acc[mt][j][3] * s1);
            if (bias) {
                float2 bb = *(const float2*)&bias[gc];
                v0.x += bb.x; v0.y += bb.y;
                v1.x += bb.x; v1.y += bb.y;
            }
            if (r0 < M) {
                if (emb) {
                    float2 e0 = *(const float2*)&emb[(size_t)r0 * 256 + gc];
                    v0.x += e0.x; v0.y += e0.y;
                }
                if (ROUND_OUT) { v0.x = tf32f(v0.x); v0.y = tf32f(v0.y); }
                *(float2*)&C[(size_t)r0 * 256 + gc] = v0;
            }
            if (r1 < M) {
                if (emb) {
                    float2 e1 = *(const float2*)&emb[(size_t)r1 * 256 + gc];
                    v1.x += e1.x; v1.y += e1.y;
                }
                if (ROUND_OUT) { v1.x = tf32f(v1.x); v1.y = tf32f(v1.y); }
                *(float2*)&C[(size_t)r1 * 256 + gc] = v1;
            }
        }
    }
    #undef ISSUE_CHUNK
}

// generic GEMM with block offset (A pre-rounded tf32): convs + MLP chunks
__global__ __launch_bounds__(256, 2) void gemm_conv(const float* __restrict__ A,
                                                    const float* __restrict__ Bt, int ldb,
                                                    const float* __restrict__ rowscale,
                                                    float* __restrict__ C, int M, int K,
                                                    int xoff) {
    extern __shared__ char smem[];
    gemm_body<false, false>(A, Bt, ldb, nullptr, nullptr, rowscale, C, M, K,
                            blockIdx.x + xoff, blockIdx.y, smem_u32(smem));
}

// input transform (dual U/P): raw fp32 A (round frags), rounded output
__global__ __launch_bounds__(256, 2) void gemm_dual_in(
    const float* __restrict__ A0, const float* __restrict__ B0,
    const float* __restrict__ bias0, const float* __restrict__ emb0,
    float* __restrict__ C0, int M0,
    const float* __restrict__ A1, const float* __restrict__ B1,
    const float* __restrict__ bias1, const float* __restrict__ emb1,
    float* __restrict__ C1, int M1,
    int ldb, int K, int split) {
    extern __shared__ char smem[];
    uint32_t sb = smem_u32(smem);
    if ((int)blockIdx.x < split)
        gemm_body<true, true>(A0, B0, ldb, bias0, emb0, nullptr, C0, M0, K,
                              blockIdx.x, blockIdx.y, sb);
    else
        gemm_body<true, true>(A1, B1, ldb, bias1, emb1, nullptr, C1, M1, K,
                              blockIdx.x - split, blockIdx.y, sb);
}

// ================= GCN aggregation chunk: nodes [n0, n0+cnt) =================
// src holds h_scaled = h*dinv.  out g_x[n] = tf32((sum_nbr + self)*dinv[n] + b)
__global__ void k_gather(const float* __restrict__ src, const float* __restrict__ b,
                         int relu, int n0, int cnt) {
    int i = blockIdx.x * blockDim.x + threadIdx.x;
    if (i >= cnt * 64) return;
    int n = n0 + (i >> 6);
    int c = (i & 63) << 2;
    float di = g_dinv[n];
    float4 acc = *(const float4*)&src[(size_t)n * D + c];
    int s0 = g_off[n];
    int s1 = s0 + g_deg[n];
    int j = s0;
    for (; j + 1 < s1; j += 2) {
        int a0 = g_adj[j];
        int a1 = g_adj[j + 1];
        float4 h0 = *(const float4*)&src[(size_t)a0 * D + c];
        float4 h1 = *(const float4*)&src[(size_t)a1 * D + c];
        acc.x += h0.x + h1.x; acc.y += h0.y + h1.y;
        acc.z += h0.z + h1.z; acc.w += h0.w + h1.w;
    }
    if (j < s1) {
        int a = g_adj[j];
        float4 hv = *(const float4*)&src[(size_t)a * D + c];
        acc.x += hv.x; acc.y += hv.y; acc.z += hv.z; acc.w += hv.w;
    }
    float4 bb = *(const float4*)&b[c];
    acc.x = acc.x * di + bb.x; acc.y = acc.y * di + bb.y;
    acc.z = acc.z * di + bb.z; acc.w = acc.w * di + bb.w;
    if (relu) {
        acc.x = fmaxf(acc.x, 0.f); acc.y = fmaxf(acc.y, 0.f);
        acc.z = fmaxf(acc.z, 0.f); acc.w = fmaxf(acc.w, 0.f);
    }
    acc.x = tf32f(acc.x); acc.y = tf32f(acc.y);
    acc.z = tf32f(acc.z); acc.w = tf32f(acc.w);
    *(float4*)&g_x[(size_t)n * D + c] = acc;
}

// ================= per-edge MLP, user-ordered (warp per user) =================
__global__ void k_edge_pred_user(const float* __restrict__ m1b,
                                 const float* __restrict__ m2W,
                                 const float* __restrict__ m2b,
                                 float* __restrict__ out) {
    int gid = blockIdx.x * blockDim.x + threadIdx.x;
    int u = gid >> 5;
    int lane = gid & 31;
    if (u >= NU) return;
    int dg = g_deg[u];
    if (dg == 0) return;
    int s0 = g_off[u];

    const float4* hu4 = (const float4*)&g_h[(size_t)u * D];
    float4 a0 = hu4[lane];
    float4 a1 = hu4[lane + 32];
    float4 bb0 = ((const float4*)m1b)[lane];
    float4 bb1 = ((const float4*)m1b)[lane + 32];
    a0.x += bb0.x; a0.y += bb0.y; a0.z += bb0.z; a0.w += bb0.w;
    a1.x += bb1.x; a1.y += bb1.y; a1.z += bb1.z; a1.w += bb1.w;
    float4 w0 = ((const float4*)m2W)[lane];
    float4 w1 = ((const float4*)m2W)[lane + 32];
    float m2bb = m2b[0];

    for (int j = s0; j < s0 + dg; j++) {
        int p = g_adj[j];
        int e = g_aid[j];
        const float4* hp4 = (const float4*)&g_h[(size_t)p * D];
        float4 b0 = hp4[lane];
        float4 b1 = hp4[lane + 32];
        float s = fmaxf(a0.x + b0.x, 0.f) * w0.x
                + fmaxf(a0.y + b0.y, 0.f) * w0.y
                + fmaxf(a0.z + b0.z, 0.f) * w0.z
                + fmaxf(a0.w + b0.w, 0.f) * w0.w
                + fmaxf(a1.x + b1.x, 0.f) * w1.x
                + fmaxf(a1.y + b1.y, 0.f) * w1.y
                + fmaxf(a1.z + b1.z, 0.f) * w1.z
                + fmaxf(a1.w + b1.w, 0.f) * w1.w;
        #pragma unroll
        for (int o = 16; o; o >>= 1) s += __shfl_down_sync(0xFFFFFFFFu, s, o);
        if (lane == 0) out[e] = s + m2bb;
    }
}

// ================= launch =================
extern "C" void kernel_launch(void* const* d_in, const int* in_sizes, int n_in,
                              void* d_out, int out_size) {
    const int*   ei   = (const int*)d_in[0];
    const float* uf   = (const float*)d_in[1];
    const float* pf   = (const float*)d_in[2];
    const float* uemb = (const float*)d_in[3];
    const float* pemb = (const float*)d_in[4];
    const float* uW   = (const float*)d_in[5];
    const float* ub   = (const float*)d_in[6];
    const float* pW   = (const float*)d_in[7];
    const float* pb   = (const float*)d_in[8];
    const float* c1W  = (const float*)d_in[9];
    const float* c1b  = (const float*)d_in[10];
    const float* c2W  = (const float*)d_in[11];
    const float* c2b  = (const float*)d_in[12];
    const float* m1W  = (const float*)d_in[13];
    const float* m1b  = (const float*)d_in[14];
    const float* m2W  = (const float*)d_in[15];
    const float* m2b  = (const float*)d_in[16];
    float* preds = (float*)d_out;

    float* xp; float* hp; float* hp2; float* wt; float* dv; int* degp; int* totp;
    cudaGetSymbolAddress((void**)&xp, g_x);
    cudaGetSymbolAddress((void**)&hp, g_h);
    cudaGetSymbolAddress((void**)&hp2, g_h2);
    cudaGetSymbolAddress((void**)&wt, g_wt);
    cudaGetSymbolAddress((void**)&dv, g_dinv);
    cudaGetSymbolAddress((void**)&degp, g_deg);
    cudaGetSymbolAddress((void**)&totp, g_total);

    static cudaStream_t s2 = nullptr;
    static cudaEvent_t evCSR, evA[3], evB[3], evD[3], evMLP;
    static bool init = false;
    if (!init) {
        cudaStreamCreateWithFlags(&s2, cudaStreamNonBlocking);
        cudaEventCreateWithFlags(&evCSR, cudaEventDisableTiming);
        cudaEventCreateWithFlags(&evMLP, cudaEventDisableTiming);
        for (int i = 0; i < 3; i++) {
            cudaEventCreateWithFlags(&evA[i], cudaEventDisableTiming);
            cudaEventCreateWithFlags(&evB[i], cudaEventDisableTiming);
            cudaEventCreateWithFlags(&evD[i], cudaEventDisableTiming);
        }
        cudaFuncSetAttribute(gemm_conv,    cudaFuncAttributeMaxDynamicSharedMemorySize, GEMM_SMEM);
        cudaFuncSetAttribute(gemm_dual_in, cudaFuncAttributeMaxDynamicSharedMemorySize, GEMM_SMEM);
        init = true;
    }

    static cudaEvent_t evFork = nullptr;
    if (!evFork) cudaEventCreateWithFlags(&evFork, cudaEventDisableTiming);

    // ---- fork: CSR build on s2 ----
    cudaEventRecord(evFork, 0);
    cudaStreamWaitEvent(s2, evFork, 0);
    cudaMemsetAsync(degp, 0, NN * sizeof(int), s2);
    cudaMemsetAsync(totp, 0, sizeof(int), s2);
    k_degree<<<(NE + 255) / 256, 256, 0, s2>>>(ei);
    k_offsets<<<(NN + 255) / 256, 256, 0, s2>>>();
    k_fill<<<(NE + 255) / 256, 256, 0, s2>>>(ei);
    cudaEventRecord(evCSR, s2);

    // ---- main stream: transposes + input transform ----
    dim3 tb(32, 8);
    k_transpose<<<dim3(8, 4),  tb>>>(uW,  wt + WT_U,  128, 256);
    k_transpose<<<dim3(8, 4),  tb>>>(pW,  wt + WT_P,  128, 256);
    k_transpose<<<dim3(8, 8),  tb>>>(c1W, wt + WT_C1, 256, 256);
    k_transpose<<<dim3(8, 8),  tb>>>(c2W, wt + WT_C2, 256, 256);
    k_transpose<<<dim3(8, 16), tb>>>(m1W, wt + WT_M1, 512, 256);

    const int gU = (NU + 127) / 128;   // 782
    const int gP = (NP + 127) / 128;   // 391
    const int gN = (NN + 127) / 128;   // 1172

    gemm_dual_in<<<dim3(gU + gP, 2), 256, GEMM_SMEM>>>(
        uf, wt + WT_U, ub, uemb, xp, NU,
        pf, wt + WT_P, pb, pemb, xp + (size_t)NU * D, NP,
        128, 128, gU);

    // conv1 full (needs dinv from CSR chain)
    cudaStreamWaitEvent(0, evCSR, 0);
    gemm_conv<<<dim3(gN, 2), 256, GEMM_SMEM>>>(xp, wt + WT_C1, 256, dv, hp, NN, 256, 0);

    // ---- stage 2 pipeline: gather1 chunks (s0) feed conv2 chunks (s2) ----
    // chunk boundaries aligned to 128-row GEMM blocks: 391/391/390 blocks
    const int blkOff[4] = {0, 391, 782, 1172};
    const int nOff[4] = {0, 391 * 128, 782 * 128, NN};   // 0, 50048, 100096, 150000
    for (int c = 0; c < 3; c++) {
        int cnt = nOff[c + 1] - nOff[c];
        k_gather<<<(cnt * 64 + 255) / 256, 256>>>(hp, c1b, 1, nOff[c], cnt);
        cudaEventRecord(evA[c], 0);
    }
    for (int c = 0; c < 3; c++) {
        cudaStreamWaitEvent(s2, evA[c], 0);
        gemm_conv<<<dim3(blkOff[c + 1] - blkOff[c], 2), 256, GEMM_SMEM, s2>>>(
            xp, wt + WT_C2, 256, dv, hp2, NN, 256, blkOff[c]);
        cudaEventRecord(evB[c], s2);
    }

    // ---- stage 3 pipeline: gather2 chunks (s0, after ALL conv2) feed MLP chunks (s2)
    cudaStreamWaitEvent(0, evB[2], 0);   // gather2 reads all of g_h2
    for (int c = 0; c < 3; c++) {
        int cnt = nOff[c + 1] - nOff[c];
        k_gather<<<(cnt * 64 + 255) / 256, 256>>>(hp2, c2b, 0, nOff[c], cnt);
        cudaEventRecord(evD[c], 0);
    }
    // MLP chunks: users blocks [0,391) need g_x rows < 50048 (chunk0);
    // users blocks [391,782) rows < 100096 (chunk1); products need chunk1+chunk2.
    cudaStreamWaitEvent(s2, evD[0], 0);
    gemm_conv<<<dim3(391, 2), 256, GEMM_SMEM, s2>>>(xp, wt + WT_M1, 512, nullptr, hp, NU, 256, 0);
    cudaStreamWaitEvent(s2, evD[1], 0);
    gemm_conv<<<dim3(gU - 391, 2), 256, GEMM_SMEM, s2>>>(xp, wt + WT_M1, 512, nullptr, hp, NU, 256, 391);
    cudaStreamWaitEvent(s2, evD[2], 0);
    gemm_conv<<<dim3(gP, 2), 256, GEMM_SMEM, s2>>>(xp + (size_t)NU * D, wt + WT_M1 + 256, 512,
                                                   nullptr, hp + (size_t)NU * D, NP, 256, 0);
    cudaEventRecord(evMLP, s2);

    // ---- edge scoring (needs all MLP partials) ----
    cudaStreamWaitEvent(0, evMLP, 0);
    k_edge_pred_user<<<(NU * 32 + 255) / 256, 256>>>(m1b, m2W, m2b, preds);
}

// round 17
// speedup vs baseline: 1.0953x; 1.0953x over previous
#include <cuda_runtime.h>
#include <cuda_fp16.h>
#include <cstdint>

#define NU 100000
#define NP 50000
#define NN 150000   // NU + NP
#define NE 250000
#define D  256

// ---------------- scratch (static device globals; no allocation) ----------------
__device__ float  g_x[(size_t)NN * D];   // conv input chain (tf32-rounded at write)
__device__ float  g_h[(size_t)NN * D];   // MLP partials (fp32)
__device__ __half g_hh[(size_t)NN * D];  // conv out h*dinv (fp16) — gather source
__device__ float g_dinv[NN];
__device__ int   g_deg[NN];
__device__ int   g_off[NN];
__device__ int   g_cur[NN];
__device__ int   g_total;
__device__ int   g_adj[2 * NE];
__device__ int   g_aid[2 * NE];
__device__ float g_wt[327680];
#define WT_U  0
#define WT_P  32768
#define WT_C1 65536
#define WT_C2 131072
#define WT_M1 196608

// ================= helpers =================
__device__ __forceinline__ uint32_t smem_u32(const void* p) {
    uint32_t a;
    asm("{ .reg .u64 t; cvta.to.shared.u64 t, %1; cvt.u32.u64 %0, t; }" : "=r"(a) : "l"(p));
    return a;
}
__device__ __forceinline__ uint32_t totf32(float x) {
    uint32_t u;
    asm("cvt.rna.tf32.f32 %0, %1;" : "=r"(u) : "f"(x));
    return u;
}
__device__ __forceinline__ uint32_t tf32r(uint32_t x) { return totf32(__uint_as_float(x)); }
__device__ __forceinline__ float tf32f(float x) { return __uint_as_float(totf32(x)); }
#define SWZ(off) ((off) ^ (((off) >> 3) & 0x70))
#define LDSM_X4(r0, r1, r2, r3, addr) \
    asm volatile("ldmatrix.sync.aligned.m8n8.x4.shared.b16 {%0, %1, %2, %3}, [%4];" \
                 : "=r"(r0), "=r"(r1), "=r"(r2), "=r"(r3) : "r"(addr))
#define MMA_TF32(c, a0, a1, a2, a3, b0, b1) \
    asm volatile("mma.sync.aligned.m16n8k8.row.col.f32.tf32.tf32.f32 " \
                 "{%0, %1, %2, %3}, {%4, %5, %6, %7}, {%8, %9}, {%0, %1, %2, %3};" \
                 : "+f"((c)[0]), "+f"((c)[1]), "+f"((c)[2]), "+f"((c)[3]) \
                 : "r"(a0), "r"(a1), "r"(a2), "r"(a3), "r"(b0), "r"(b1))
#define CP_ASYNC16(dst, src, sz) \
    asm volatile("cp.async.cg.shared.global [%0], [%1], 16, %2;" \
                 :: "r"(dst), "l"(src), "r"(sz) : "memory")
#define CP_COMMIT() asm volatile("cp.async.commit_group;" ::: "memory")
#define CP_WAIT1()  asm volatile("cp.async.wait_group 1;" ::: "memory")

// ================= degree / CSR build =================
__global__ void k_degree(const int* __restrict__ ei) {
    int e = blockIdx.x * blockDim.x + threadIdx.x;
    if (e < NE) {
        atomicAdd(&g_deg[ei[e]], 1);
        atomicAdd(&g_deg[ei[NE + e]], 1);
    }
}
__global__ void k_offsets() {
    int n = blockIdx.x * blockDim.x + threadIdx.x;
    int lane = threadIdx.x & 31;
    int d = (n < NN) ? g_deg[n] : 0;
    int incl = d;
    #pragma unroll
    for (int o = 1; o < 32; o <<= 1) {
        int t = __shfl_up_sync(0xFFFFFFFFu, incl, o);
        if (lane >= o) incl += t;
    }
    int excl = incl - d;
    int base = 0;
    if (lane == 31) base = atomicAdd(&g_total, incl);
    base = __shfl_sync(0xFFFFFFFFu, base, 31);
    if (n < NN) {
        g_off[n] = base + excl;
        g_cur[n] = 0;
        g_dinv[n] = rsqrtf((float)d + 1.0f);
    }
}
__global__ void k_fill(const int* __restrict__ ei) {
    int e = blockIdx.x * blockDim.x + threadIdx.x;
    if (e >= NE) return;
    int u = ei[e];
    int p = ei[NE + e];
    int idx = g_off[p] + atomicAdd(&g_cur[p], 1);
    g_adj[idx] = u;  g_aid[idx] = e;
    int idx2 = g_off[u] + atomicAdd(&g_cur[u], 1);
    g_adj[idx2] = p; g_aid[idx2] = e;
}

// ========= weight transpose + tf32 pre-round =========
__global__ void k_transpose(const float* __restrict__ W, float* __restrict__ Wt, int K, int N) {
    __shared__ float t[32][33];
    int bn = blockIdx.x * 32, bk = blockIdx.y * 32;
    #pragma unroll
    for (int i = 0; i < 4; i++) {
        int k = bk + threadIdx.y + i * 8, n = bn + threadIdx.x;
        if (k < K && n < N) t[threadIdx.y + i * 8][threadIdx.x] = W[(size_t)k * N + n];
    }
    __syncthreads();
    #pragma unroll
    for (int i = 0; i < 4; i++) {
        int n = bn + threadIdx.y + i * 8, k = bk + threadIdx.x;
        if (k < K && n < N)
            Wt[(size_t)n * K + k] = tf32f(t[threadIdx.x][threadIdx.y + i * 8]);
    }
}

// ================= tf32 mma.sync GEMM body =================
// ROUND_A: tf32-round A fragments (raw fp32 A sources only).
// ROUND_OUT: tf32-round fp32 output (feeds another GEMM's A operand).
// HALF_OUT: write output as fp16 (conv intermediate; precision == tf32 mantissa).
#define NSTAGE 3
#define STAGE_BYTES 32768
#define GEMM_SMEM (NSTAGE * STAGE_BYTES)

template<bool ROUND_A, bool ROUND_OUT, bool HALF_OUT>
__device__ __forceinline__ void gemm_body(const float* __restrict__ A,
                                          const float* __restrict__ Bt, int ldb,
                                          const float* __restrict__ bias,
                                          const float* __restrict__ emb,
                                          const float* __restrict__ rowscale,
                                          void* __restrict__ C,
                                          int M, int K, int blkx, int blky,
                                          uint32_t sb) {
    int tid = threadIdx.x;
    int lane = tid & 31;
    int wid = tid >> 5;
    int warpM = wid & 3;
    int warpN = wid >> 2;
    int rowBase = blkx * 128;
    int colBase = blky * 128;

    float acc[2][8][4];
    #pragma unroll
    for (int mt = 0; mt < 2; mt++)
        #pragma unroll
        for (int j = 0; j < 8; j++)
            #pragma unroll
            for (int q = 0; q < 4; q++) acc[mt][j][q] = 0.f;

    const int fr  = tid >> 3;
    const int fc4 = tid & 7;
    const float* aSrcBase = A  + (size_t)(rowBase + fr) * K + fc4 * 4;
    const float* bSrcBase = Bt + (size_t)(colBase + fr) * ldb + fc4 * 4;

    #define ISSUE_CHUNK(c)                                                         \
        {                                                                          \
            int k0 = (c) << 5;                                                     \
            uint32_t abase = sb + ((c) % NSTAGE) * STAGE_BYTES;                    \
            uint32_t bbase = abase + 16384;                                        \
            _Pragma("unroll")                                                      \
            for (int i = 0; i < 4; i++) {                                          \
                int r = fr + i * 32;                                               \
                uint32_t off = SWZ((uint32_t)(r * 128 + fc4 * 16));                \
                uint32_t asz = (rowBase + r < M) ? 16u : 0u;                       \
                CP_ASYNC16(abase + off, aSrcBase + (size_t)(i * 32) * K + k0, asz);\
                CP_ASYNC16(bbase + off, bSrcBase + (size_t)(i * 32) * ldb + k0, 16u);\
            }                                                                      \
        }

    const int arow = warpM * 32 + (lane & 15);
    const int achunkoff = (lane >> 4);
    const int brow = warpN * 64 + ((lane >> 4) << 3) + (lane & 7);
    const int bchunkoff = ((lane >> 3) & 1);

    const int CH = K >> 5;
    ISSUE_CHUNK(0); CP_COMMIT();
    if (CH > 1) { ISSUE_CHUNK(1); }
    CP_COMMIT();

    for (int ch = 0; ch < CH; ch++) {
        CP_WAIT1();
        __syncthreads();
        if (ch + NSTAGE - 1 < CH) { ISSUE_CHUNK(ch + NSTAGE - 1); }
        CP_COMMIT();

        uint32_t abase = sb + (ch % NSTAGE) * STAGE_BYTES;
        uint32_t bbase = abase + 16384;
        #pragma unroll
        for (int ks = 0; ks < 4; ks++) {
            uint32_t af[2][4];
            #pragma unroll
            for (int mt = 0; mt < 2; mt++) {
                int r = arow + mt * 16;
                uint32_t addr = abase + SWZ((uint32_t)(r * 128 + (2 * ks + achunkoff) * 16));
                LDSM_X4(af[mt][0], af[mt][1], af[mt][2], af[mt][3], addr);
                if (ROUND_A) {
                    #pragma unroll
                    for (int q = 0; q < 4; q++) af[mt][q] = tf32r(af[mt][q]);
                }
            }
            uint32_t bf[4][4];
            #pragma unroll
            for (int jp = 0; jp < 4; jp++) {
                int r = brow + jp * 16;
                uint32_t addr = bbase + SWZ((uint32_t)(r * 128 + (2 * ks + bchunkoff) * 16));
                LDSM_X4(bf[jp][0], bf[jp][1], bf[jp][2], bf[jp][3], addr);
            }
            #pragma unroll
            for (int mt = 0; mt < 2; mt++)
                #pragma unroll
                for (int j = 0; j < 8; j++)
                    MMA_TF32(acc[mt][j], af[mt][0], af[mt][1], af[mt][2], af[mt][3],
                             bf[j >> 1][(j & 1) * 2], bf[j >> 1][(j & 1) * 2 + 1]);
        }
    }

    #pragma unroll
    for (int mt = 0; mt < 2; mt++) {
        int r0 = rowBase + warpM * 32 + mt * 16 + (lane >> 2);
        int r1 = r0 + 8;
        float s0 = (rowscale && r0 < M) ? rowscale[r0] : 1.f;
        float s1 = (rowscale && r1 < M) ? rowscale[r1] : 1.f;
        #pragma unroll
        for (int j = 0; j < 8; j++) {
            int gc = colBase + warpN * 64 + j * 8 + (lane & 3) * 2;
            float2 v0 = make_float2(acc[mt][j][0] * s0, acc[mt][j][1] * s0);
            float2 v1 = make_float2(acc[mt][j][2] * s1, acc[mt][j][3] * s1);
            if (bias) {
                float2 bb = *(const float2*)&bias[gc];
                v0.x += bb.x; v0.y += bb.y;
                v1.x += bb.x; v1.y += bb.y;
            }
            if (r0 < M) {
                if (emb) {
                    float2 e0 = *(const float2*)&emb[(size_t)r0 * 256 + gc];
                    v0.x += e0.x; v0.y += e0.y;
                }
                if (HALF_OUT) {
                    *(__half2*)&((__half*)C)[(size_t)r0 * 256 + gc] =
                        __floats2half2_rn(v0.x, v0.y);
                } else {
                    if (ROUND_OUT) { v0.x = tf32f(v0.x); v0.y = tf32f(v0.y); }
                    *(float2*)&((float*)C)[(size_t)r0 * 256 + gc] = v0;
                }
            }
            if (r1 < M) {
                if (emb) {
                    float2 e1 = *(const float2*)&emb[(size_t)r1 * 256 + gc];
                    v1.x += e1.x; v1.y += e1.y;
                }
                if (HALF_OUT) {
                    *(__half2*)&((__half*)C)[(size_t)r1 * 256 + gc] =
                        __floats2half2_rn(v1.x, v1.y);
                } else {
                    if (ROUND_OUT) { v1.x = tf32f(v1.x); v1.y = tf32f(v1.y); }
                    *(float2*)&((float*)C)[(size_t)r1 * 256 + gc] = v1;
                }
            }
        }
    }
    #undef ISSUE_CHUNK
}

// conv GEMM: A = g_x (pre-rounded), out = fp16 h*dinv
__global__ __launch_bounds__(256, 2) void gemm_conv(const float* __restrict__ A,
                                                    const float* __restrict__ Bt, int ldb,
                                                    const float* __restrict__ rowscale,
                                                    __half* __restrict__ C, int M, int K) {
    extern __shared__ char smem[];
    gemm_body<false, false, true>(A, Bt, ldb, nullptr, nullptr, rowscale, C, M, K,
                                  blockIdx.x, blockIdx.y, smem_u32(smem));
}

// input transform (dual U/P): raw fp32 A (round frags), rounded fp32 output
__global__ __launch_bounds__(256, 2) void gemm_dual_in(
    const float* __restrict__ A0, const float* __restrict__ B0,
    const float* __restrict__ bias0, const float* __restrict__ emb0,
    float* __restrict__ C0, int M0,
    const float* __restrict__ A1, const float* __restrict__ B1,
    const float* __restrict__ bias1, const float* __restrict__ emb1,
    float* __restrict__ C1, int M1,
    int ldb, int K, int split) {
    extern __shared__ char smem[];
    uint32_t sb = smem_u32(smem);
    if ((int)blockIdx.x < split)
        gemm_body<true, true, false>(A0, B0, ldb, bias0, emb0, nullptr, C0, M0, K,
                                     blockIdx.x, blockIdx.y, sb);
    else
        gemm_body<true, true, false>(A1, B1, ldb, bias1, emb1, nullptr, C1, M1, K,
                                     blockIdx.x - split, blockIdx.y, sb);
}

// MLP partials (dual U/P): A = g_x (pre-rounded), out fp32 (feeds edge_pred)
__global__ __launch_bounds__(256, 2) void gemm_dual_mlp(
    const float* __restrict__ A0, const float* __restrict__ B0,
    float* __restrict__ C0, int M0,
    const float* __restrict__ A1, const float* __restrict__ B1,
    float* __restrict__ C1, int M1,
    int ldb, int K, int split) {
    extern __shared__ char smem[];
    uint32_t sb = smem_u32(smem);
    if ((int)blockIdx.x < split)
        gemm_body<false, false, false>(A0, B0, ldb, nullptr, nullptr, nullptr, C0, M0, K,
                                       blockIdx.x, blockIdx.y, sb);
    else
        gemm_body<false, false, false>(A1, B1, ldb, nullptr, nullptr, nullptr, C1, M1, K,
                                       blockIdx.x - split, blockIdx.y, sb);
}

// ================= fused GCN aggregation (CSR row-sum of fp16 h_scaled) ==========
// out g_x[n] = tf32((sum_nbr + self) * dinv[n] + b)
__global__ void k_gather(const float* __restrict__ b, int relu) {
    int i = blockIdx.x * blockDim.x + threadIdx.x;
    if (i >= NN * 64) return;
    int n = i >> 6;
    int c = (i & 63) << 2;
    float di = g_dinv[n];

    const __half* src = g_hh;
    uint2 sv = *(const uint2*)&src[(size_t)n * D + c];
    float2 f0 = __half22float2(*(__half2*)&sv.x);
    float2 f1 = __half22float2(*(__half2*)&sv.y);
    float4 acc = make_float4(f0.x, f0.y, f1.x, f1.y);

    int s0 = g_off[n];
    int s1 = s0 + g_deg[n];
    int j = s0;
    for (; j + 1 < s1; j += 2) {
        int a0 = g_adj[j];
        int a1 = g_adj[j + 1];
        uint2 v0 = *(const uint2*)&src[(size_t)a0 * D + c];
        uint2 v1 = *(const uint2*)&src[(size_t)a1 * D + c];
        float2 p00 = __half22float2(*(__half2*)&v0.x);
        float2 p01 = __half22float2(*(__half2*)&v0.y);
        float2 p10 = __half22float2(*(__half2*)&v1.x);
        float2 p11 = __half22float2(*(__half2*)&v1.y);
        acc.x += p00.x + p10.x; acc.y += p00.y + p10.y;
        acc.z += p01.x + p11.x; acc.w += p01.y + p11.y;
    }
    if (j < s1) {
        int a = g_adj[j];
        uint2 v = *(const uint2*)&src[(size_t)a * D + c];
        float2 p0 = __half22float2(*(__half2*)&v.x);
        float2 p1 = __half22float2(*(__half2*)&v.y);
        acc.x += p0.x; acc.y += p0.y; acc.z += p1.x; acc.w += p1.y;
    }
    float4 bb = *(const float4*)&b[c];
    acc.x = acc.x * di + bb.x; acc.y = acc.y * di + bb.y;
    acc.z = acc.z * di + bb.z; acc.w = acc.w * di + bb.w;
    if (relu) {
        acc.x = fmaxf(acc.x, 0.f); acc.y = fmaxf(acc.y, 0.f);
        acc.z = fmaxf(acc.z, 0.f); acc.w = fmaxf(acc.w, 0.f);
    }
    acc.x = tf32f(acc.x); acc.y = tf32f(acc.y);
    acc.z = tf32f(acc.z); acc.w = tf32f(acc.w);
    *(float4*)&g_x[(size_t)n * D + c] = acc;
}

// ================= per-edge MLP, user-ordered (warp per user) =================
__global__ void k_edge_pred_user(const float* __restrict__ m1b,
                                 const float* __restrict__ m2W,
                                 const float* __restrict__ m2b,
                                 float* __restrict__ out) {
    int gid = blockIdx.x * blockDim.x + threadIdx.x;
    int u = gid >> 5;
    int lane = gid & 31;
    if (u >= NU) return;
    int dg = g_deg[u];
    if (dg == 0) return;
    int s0 = g_off[u];

    const float4* hu4 = (const float4*)&g_h[(size_t)u * D];
    float4 a0 = hu4[lane];
    float4 a1 = hu4[lane + 32];
    float4 bb0 = ((const float4*)m1b)[lane];
    float4 bb1 = ((const float4*)m1b)[lane + 32];
    a0.x += bb0.x; a0.y += bb0.y; a0.z += bb0.z; a0.w += bb0.w;
    a1.x += bb1.x; a1.y += bb1.y; a1.z += bb1.z; a1.w += bb1.w;
    float4 w0 = ((const float4*)m2W)[lane];
    float4 w1 = ((const float4*)m2W)[lane + 32];
    float m2bb = m2b[0];

    for (int j = s0; j < s0 + dg; j++) {
        int p = g_adj[j];
        int e = g_aid[j];
        const float4* hp4 = (const float4*)&g_h[(size_t)p * D];
        float4 b0 = hp4[lane];
        float4 b1 = hp4[lane + 32];
        float s = fmaxf(a0.x + b0.x, 0.f) * w0.x
                + fmaxf(a0.y + b0.y, 0.f) * w0.y
                + fmaxf(a0.z + b0.z, 0.f) * w0.z
                + fmaxf(a0.w + b0.w, 0.f) * w0.w
                + fmaxf(a1.x + b1.x, 0.f) * w1.x
                + fmaxf(a1.y + b1.y, 0.f) * w1.y
                + fmaxf(a1.z + b1.z, 0.f) * w1.z
                + fmaxf(a1.w + b1.w, 0.f) * w1.w;
        #pragma unroll
        for (int o = 16; o; o >>= 1) s += __shfl_down_sync(0xFFFFFFFFu, s, o);
        if (lane == 0) out[e] = s + m2bb;
    }
}

// ================= launch =================
extern "C" void kernel_launch(void* const* d_in, const int* in_sizes, int n_in,
                              void* d_out, int out_size) {
    const int*   ei   = (const int*)d_in[0];
    const float* uf   = (const float*)d_in[1];
    const float* pf   = (const float*)d_in[2];
    const float* uemb = (const float*)d_in[3];
    const float* pemb = (const float*)d_in[4];
    const float* uW   = (const float*)d_in[5];
    const float* ub   = (const float*)d_in[6];
    const float* pW   = (const float*)d_in[7];
    const float* pb   = (const float*)d_in[8];
    const float* c1W  = (const float*)d_in[9];
    const float* c1b  = (const float*)d_in[10];
    const float* c2W  = (const float*)d_in[11];
    const float* c2b  = (const float*)d_in[12];
    const float* m1W  = (const float*)d_in[13];
    const float* m1b  = (const float*)d_in[14];
    const float* m2W  = (const float*)d_in[15];
    const float* m2b  = (const float*)d_in[16];
    float* preds = (float*)d_out;

    float* xp; float* hp; __half* hhp; float* wt; float* dv; int* degp; int* totp;
    cudaGetSymbolAddress((void**)&xp, g_x);
    cudaGetSymbolAddress((void**)&hp, g_h);
    cudaGetSymbolAddress((void**)&hhp, g_hh);
    cudaGetSymbolAddress((void**)&wt, g_wt);
    cudaGetSymbolAddress((void**)&dv, g_dinv);
    cudaGetSymbolAddress((void**)&degp, g_deg);
    cudaGetSymbolAddress((void**)&totp, g_total);

    static cudaStream_t s2 = nullptr;
    static cudaEvent_t evFork = nullptr, evCSR = nullptr;
    static bool attrSet = false;
    if (!s2) {
        cudaStreamCreateWithFlags(&s2, cudaStreamNonBlocking);
        cudaEventCreateWithFlags(&evFork, cudaEventDisableTiming);
        cudaEventCreateWithFlags(&evCSR, cudaEventDisableTiming);
    }
    if (!attrSet) {
        cudaFuncSetAttribute(gemm_conv,     cudaFuncAttributeMaxDynamicSharedMemorySize, GEMM_SMEM);
        cudaFuncSetAttribute(gemm_dual_in,  cudaFuncAttributeMaxDynamicSharedMemorySize, GEMM_SMEM);
        cudaFuncSetAttribute(gemm_dual_mlp, cudaFuncAttributeMaxDynamicSharedMemorySize, GEMM_SMEM);
        attrSet = true;
    }

    // ---- fork: CSR build on s2 ----
    cudaEventRecord(evFork, 0);
    cudaStreamWaitEvent(s2, evFork, 0);
    cudaMemsetAsync(degp, 0, NN * sizeof(int), s2);
    cudaMemsetAsync(totp, 0, sizeof(int), s2);
    k_degree<<<(NE + 255) / 256, 256, 0, s2>>>(ei);
    k_offsets<<<(NN + 255) / 256, 256, 0, s2>>>();
    k_fill<<<(NE + 255) / 256, 256, 0, s2>>>(ei);
    cudaEventRecord(evCSR, s2);

    // ---- main stream: transposes ----
    dim3 tb(32, 8);
    k_transpose<<<dim3(8, 4),  tb>>>(uW,  wt + WT_U,  128, 256);
    k_transpose<<<dim3(8, 4),  tb>>>(pW,  wt + WT_P,  128, 256);
    k_transpose<<<dim3(8, 8),  tb>>>(c1W, wt + WT_C1, 256, 256);
    k_transpose<<<dim3(8, 8),  tb>>>(c2W, wt + WT_C2, 256, 256);
    k_transpose<<<dim3(8, 16), tb>>>(m1W, wt + WT_M1, 512, 256);

    const int gU = (NU + 127) / 128;
    const int gP = (NP + 127) / 128;
    const int gN = (NN + 127) / 128;
    const int nElem = (NN * 64 + 255) / 256;

    // input transforms (merged U+P): x = tf32(feats @ W + b + emb)
    gemm_dual_in<<<dim3(gU + gP, 2), 256, GEMM_SMEM>>>(
        uf, wt + WT_U, ub, uemb, xp, NU,
        pf, wt + WT_P, pb, pemb, xp + (size_t)NU * D, NP,
        128, 128, gU);

    // conv1 (relu): GEMM writes fp16 h*dinv ; epilogue + gather need dinv/CSR from s2
    cudaStreamWaitEvent(0, evCSR, 0);
    gemm_conv<<<dim3(gN, 2), 256, GEMM_SMEM>>>(xp, wt + WT_C1, 256, dv, hhp, NN, 256);
    k_gather<<<nElem, 256>>>(c1b, 1);

    // conv2 (no relu)
    gemm_conv<<<dim3(gN, 2), 256, GEMM_SMEM>>>(xp, wt + WT_C2, 256, dv, hhp, NN, 256);
    k_gather<<<nElem, 256>>>(c2b, 0);

    // MLP factored through nodes (merged U+P)
    gemm_dual_mlp<<<dim3(gU + gP, 2), 256, GEMM_SMEM>>>(
        xp, wt + WT_M1, hp, NU,
        xp + (size_t)NU * D, wt + WT_M1 + 256, hp + (size_t)NU * D, NP,
        512, 256, gU);

    // per-edge scoring, user-ordered
    k_edge_pred_user<<<(NU * 32 + 255) / 256, 256>>>(m1b, m2W, m2b, preds);
}